// round 6
// baseline (speedup 1.0000x reference)
#include <cuda_runtime.h>
#include <math.h>
#include <stdint.h>

// Problem dims (fixed by the dataset)
#define BB 32
#define SS 4096
#define HH 1024
#define ROWS (BB * SS)        // 131072

// Scratch (no allocations allowed)
__device__ float g_h[ROWS];
__device__ float g_min[BB];
__device__ float g_max[BB];
__device__ int   g_mflag;     // 0 = uint8 mask, 1 = int32, 2 = float32

// ---------------------------------------------------------------------------
// Kernel 0: detect mask dtype. Reference forces mask[:, :2] = True, so
// element index 1 is guaranteed truthy. Byte layouts of element 1:
//   uint8  : byte[1] == 1
//   int32  : elem1 as int == 1
//   float32: elem1 as int == 0x3F800000
// ---------------------------------------------------------------------------
__global__ void detect_kernel(const uint8_t* __restrict__ m)
{
    if (m[1] == 1) {
        g_mflag = 0;
    } else {
        int v = reinterpret_cast<const int*>(m)[1];
        g_mflag = (v == 1) ? 1 : 2;
    }
}

__device__ __forceinline__ bool mask_at(const void* m, int i, int flag)
{
    if (flag == 0) return reinterpret_cast<const uint8_t*>(m)[i] != 0;
    if (flag == 1) return reinterpret_cast<const int*>(m)[i] != 0;
    return reinterpret_cast<const float*>(m)[i] != 0.0f;
}

// ---------------------------------------------------------------------------
// Kernel 1: h[row] = dot(x[row, :], W) + bias.  One warp per row.
// Each lane: 8 x float4 coalesced loads of x; W stays in L1.
// ---------------------------------------------------------------------------
__global__ __launch_bounds__(256) void proj_kernel(
    const float* __restrict__ x,
    const float* __restrict__ W,
    const float* __restrict__ bias)
{
    const int warp = (blockIdx.x * blockDim.x + threadIdx.x) >> 5;
    const int lane = threadIdx.x & 31;

    const float4* __restrict__ xr = reinterpret_cast<const float4*>(x) + (size_t)warp * (HH / 4);
    const float4* __restrict__ Wv = reinterpret_cast<const float4*>(W);

    float acc = 0.0f;
#pragma unroll
    for (int k = 0; k < HH / 128; k++) {       // 8 iterations
        float4 xv = xr[k * 32 + lane];
        float4 wv = Wv[k * 32 + lane];
        acc = fmaf(xv.x, wv.x, acc);
        acc = fmaf(xv.y, wv.y, acc);
        acc = fmaf(xv.z, wv.z, acc);
        acc = fmaf(xv.w, wv.w, acc);
    }
#pragma unroll
    for (int o = 16; o; o >>= 1)
        acc += __shfl_xor_sync(0xffffffffu, acc, o);

    if (lane == 0)
        g_h[warp] = acc + bias[0];
}

// ---------------------------------------------------------------------------
// Kernel 2: per-b masked min/max of h over S.  One block per b.
// ---------------------------------------------------------------------------
__global__ __launch_bounds__(256) void minmax_kernel(const void* __restrict__ mask)
{
    const int b = blockIdx.x;
    const int tid = threadIdx.x;
    const int flag = g_mflag;
    const float* __restrict__ hrow = g_h + (size_t)b * SS;

    float mn = INFINITY, mx = -INFINITY;
    for (int s = tid; s < SS; s += 256) {
        if (mask_at(mask, b * SS + s, flag)) {
            float v = hrow[s];
            mn = fminf(mn, v);
            mx = fmaxf(mx, v);
        }
    }
#pragma unroll
    for (int o = 16; o; o >>= 1) {
        mn = fminf(mn, __shfl_xor_sync(0xffffffffu, mn, o));
        mx = fmaxf(mx, __shfl_xor_sync(0xffffffffu, mx, o));
    }

    __shared__ float smn[8], smx[8];
    const int wid = tid >> 5;
    if ((tid & 31) == 0) { smn[wid] = mn; smx[wid] = mx; }
    __syncthreads();

    if (wid == 0) {
        const int lane = tid & 31;
        mn = (lane < 8) ? smn[lane] : INFINITY;
        mx = (lane < 8) ? smx[lane] : -INFINITY;
#pragma unroll
        for (int o = 4; o; o >>= 1) {
            mn = fminf(mn, __shfl_xor_sync(0xffffffffu, mn, o));
            mx = fmaxf(mx, __shfl_xor_sync(0xffffffffu, mx, o));
        }
        if (lane == 0) { g_min[b] = mn; g_max[b] = mx; }
    }
}

// ---------------------------------------------------------------------------
// Kernel 3: out[i] = mask[i] ? (h[i]-mn)/(mx-mn) : 0
// (mean/std of the reference cancel algebraically:
//   (z - zmin)/(zmax - zmin) == (h - hmin)/(hmax - hmin) over the mask)
// ---------------------------------------------------------------------------
__global__ __launch_bounds__(256) void finalize_kernel(
    const void* __restrict__ mask,
    float* __restrict__ out)
{
    const int i = blockIdx.x * 256 + threadIdx.x;
    const int b = i >> 12;                    // i / 4096
    const int flag = g_mflag;
    const float mn = g_min[b];
    const float inv = 1.0f / (g_max[b] - mn);
    out[i] = mask_at(mask, i, flag) ? (g_h[i] - mn) * inv : 0.0f;
}

// ---------------------------------------------------------------------------
extern "C" void kernel_launch(void* const* d_in, const int* in_sizes, int n_in,
                              void* d_out, int out_size)
{
    // Bind inputs by element count (all four counts are distinct):
    //   input = 33554432, mask = 131072, W = 1024, b = 1
    const float* x    = nullptr;
    const void*  mask = nullptr;
    const float* W    = nullptr;
    const float* bias = nullptr;
    for (int i = 0; i < n_in; i++) {
        switch (in_sizes[i]) {
            case ROWS * (HH / 1) / 1: break; // placeholder (not used)
        }
        if      (in_sizes[i] == BB * SS * HH) x    = (const float*)d_in[i];
        else if (in_sizes[i] == BB * SS)      mask = d_in[i];
        else if (in_sizes[i] == HH)           W    = (const float*)d_in[i];
        else if (in_sizes[i] == 1)            bias = (const float*)d_in[i];
    }
    float* out = (float*)d_out;
    (void)out_size;

    detect_kernel<<<1, 1>>>((const uint8_t*)mask);
    proj_kernel<<<ROWS / 8, 256>>>(x, W, bias);     // 1 warp per row
    minmax_kernel<<<BB, 256>>>(mask);
    finalize_kernel<<<ROWS / 256, 256>>>(mask, out);
}